// round 5
// baseline (speedup 1.0000x reference)
#include <cuda_runtime.h>

// DeepFilter: out_r = box3x5( xr*fr - xi*fi ),  out_i = 2 * box3x5( xr*fi )
// Smem-free: time halo via warp shuffles, freq via rolling 3-row window.
// Each warp owns 8 output d-rows, streams 10 input rows. Interior warps take
// a fully-unpredicated fast path (warp-uniform branch).
// Shapes: B=8, D=256, T=2048, L=2, I=1. Output [B, 2D, T].

static constexpr int Bn = 8;
static constexpr int Dn = 256;
static constexpr int Tn = 2048;

static constexpr int NTHREADS = 128;   // 4 warps
static constexpr int T_TILE   = 128;   // 32 lanes x float4
static constexpr int D_STRIP  = 8;     // output rows per warp
static constexpr int D_TILE   = (NTHREADS / 32) * D_STRIP;   // 32 rows / block

__device__ __forceinline__ float4 ld4(const float* p) {
    return *reinterpret_cast<const float4*>(p);
}
__device__ __forceinline__ float2 ld2(const float* p) {
    return *reinterpret_cast<const float2*>(p);
}

template <bool DEDGE>
__device__ __forceinline__ void run_strip(const float* __restrict__ xr,
                                          const float* __restrict__ xi,
                                          const float* __restrict__ fr,
                                          const float* __restrict__ fi,
                                          float* __restrict__ out,
                                          size_t base, size_t ob,
                                          int dbase, int t, int lane,
                                          int ht, bool hlane, bool hok_t)
{
    float4 m1r = {0,0,0,0}, m1i = {0,0,0,0};
    float4 m2r = {0,0,0,0}, m2i = {0,0,0,0};
    const size_t oI = (size_t)Dn * Tn;

    #pragma unroll
    for (int r = 0; r < D_STRIP + 2; ++r) {
        const int d = dbase - 1 + r;

        float4 a, c, e, f;
        float2 ha = {0,0}, hc = {0,0}, he = {0,0}, hf = {0,0};

        if (DEDGE) {
            a = make_float4(0,0,0,0); c = a; e = a; f = a;
            if ((unsigned)d < (unsigned)Dn) {
                const size_t idx = base + (size_t)d * Tn + t;
                a = ld4(xr + idx); c = ld4(xi + idx);
                e = ld4(fr + idx); f = ld4(fi + idx);
                if (hlane & hok_t) {
                    const size_t hidx = base + (size_t)d * Tn + ht;
                    ha = ld2(xr + hidx); hc = ld2(xi + hidx);
                    he = ld2(fr + hidx); hf = ld2(fi + hidx);
                }
            }
        } else {
            // interior: row d always in-bounds; loads unconditional
            const size_t idx = base + (size_t)d * Tn + t;
            a = ld4(xr + idx); c = ld4(xi + idx);
            e = ld4(fr + idx); f = ld4(fi + idx);
            if (hlane & hok_t) {
                const size_t hidx = base + (size_t)d * Tn + ht;
                ha = ld2(xr + hidx); hc = ld2(xi + hidx);
                he = ld2(fr + hidx); hf = ld2(fi + hidx);
            }
        }

        // pointwise products (imag WITHOUT the 2x — folded into store)
        const float pr0 = fmaf(a.x, e.x, -c.x * f.x);
        const float pr1 = fmaf(a.y, e.y, -c.y * f.y);
        const float pr2 = fmaf(a.z, e.z, -c.z * f.z);
        const float pr3 = fmaf(a.w, e.w, -c.w * f.w);
        const float pi0 = a.x * f.x;
        const float pi1 = a.y * f.y;
        const float pi2 = a.z * f.z;
        const float pi3 = a.w * f.w;

        const float hpr0 = fmaf(ha.x, he.x, -hc.x * hf.x);
        const float hpr1 = fmaf(ha.y, he.y, -hc.y * hf.y);
        const float hpi0 = ha.x * hf.x;
        const float hpi1 = ha.y * hf.y;

        // neighbor exchange: lm* = p[-2],p[-1]; rp* = p[+4],p[+5]
        float lmr2 = __shfl_up_sync(0xffffffffu, pr2, 1);
        float lmr1 = __shfl_up_sync(0xffffffffu, pr3, 1);
        float rpr4 = __shfl_down_sync(0xffffffffu, pr0, 1);
        float rpr5 = __shfl_down_sync(0xffffffffu, pr1, 1);
        float lmi2 = __shfl_up_sync(0xffffffffu, pi2, 1);
        float lmi1 = __shfl_up_sync(0xffffffffu, pi3, 1);
        float rpi4 = __shfl_down_sync(0xffffffffu, pi0, 1);
        float rpi5 = __shfl_down_sync(0xffffffffu, pi1, 1);
        if (lane == 0)  { lmr2 = hpr0; lmr1 = hpr1; lmi2 = hpi0; lmi1 = hpi1; }
        if (lane == 31) { rpr4 = hpr0; rpr5 = hpr1; rpi4 = hpi0; rpi5 = hpi1; }

        // sliding 5-tap time sums
        float4 sr, si;
        sr.x = lmr2 + lmr1 + pr0 + pr1 + pr2;
        sr.y = sr.x - lmr2 + pr3;
        sr.z = sr.y - lmr1 + rpr4;
        sr.w = sr.z - pr0 + rpr5;
        si.x = lmi2 + lmi1 + pi0 + pi1 + pi2;
        si.y = si.x - lmi2 + pi3;
        si.z = si.y - lmi1 + rpi4;
        si.w = si.z - pi0 + rpi5;

        // rolling 3-row freq sum: emit output row dbase + r - 2
        if (r >= 2) {
            const int d_out = dbase + r - 2;
            float4 orr, oii;
            orr.x = m2r.x + m1r.x + sr.x;
            orr.y = m2r.y + m1r.y + sr.y;
            orr.z = m2r.z + m1r.z + sr.z;
            orr.w = m2r.w + m1r.w + sr.w;
            oii.x = 2.f * (m2i.x + m1i.x + si.x);
            oii.y = 2.f * (m2i.y + m1i.y + si.y);
            oii.z = 2.f * (m2i.z + m1i.z + si.z);
            oii.w = 2.f * (m2i.w + m1i.w + si.w);
            const size_t o = ob + (size_t)d_out * Tn + t;
            __stcs(reinterpret_cast<float4*>(out + o),      orr);
            __stcs(reinterpret_cast<float4*>(out + o + oI), oii);
        }
        m2r = m1r; m2i = m1i;
        m1r = sr;  m1i = si;
    }
}

__global__ __launch_bounds__(NTHREADS, 8)
void deepfilter_kernel(const float* __restrict__ xr,
                       const float* __restrict__ xi,
                       const float* __restrict__ fr,
                       const float* __restrict__ fi,
                       float* __restrict__ out)
{
    const int b    = blockIdx.z;
    const int t0   = blockIdx.x * T_TILE;
    const int d0   = blockIdx.y * D_TILE;
    const int warp = threadIdx.x >> 5;
    const int lane = threadIdx.x & 31;
    const int t    = t0 + 4 * lane;

    const size_t base  = (size_t)b * Dn * Tn;
    const size_t ob    = (size_t)b * (2 * Dn) * Tn;
    const int    dbase = d0 + D_STRIP * warp;   // rows dbase .. dbase+7

    // Warp-edge time halo: lane 0 needs cols t0-2,t0-1; lane 31 needs
    // t0+128,t0+129. Both 8B-aligned float2 loads used identically.
    const int  ht    = (lane == 0) ? (t0 - 2) : (t0 + T_TILE);
    const bool hlane = (lane == 0) | (lane == 31);
    const bool hok_t = (ht >= 0) & (ht < Tn);

    // d-edge only for the first and last strips of the whole D range —
    // warp-uniform, so this branch costs nothing in divergence.
    const bool dedge = (dbase == 0) | (dbase + D_STRIP == Dn);

    if (dedge) {
        run_strip<true >(xr, xi, fr, fi, out, base, ob, dbase, t, lane,
                         ht, hlane, hok_t);
    } else {
        run_strip<false>(xr, xi, fr, fi, out, base, ob, dbase, t, lane,
                         ht, hlane, hok_t);
    }
}

extern "C" void kernel_launch(void* const* d_in, const int* in_sizes, int n_in,
                              void* d_out, int out_size)
{
    (void)in_sizes; (void)n_in; (void)out_size;
    const float* xr = (const float*)d_in[0];
    const float* xi = (const float*)d_in[1];
    const float* fr = (const float*)d_in[2];
    const float* fi = (const float*)d_in[3];
    float* out = (float*)d_out;

    dim3 grid(Tn / T_TILE, Dn / D_TILE, Bn);   // (16, 8, 8) = 1024 blocks
    deepfilter_kernel<<<grid, NTHREADS>>>(xr, xi, fr, fi, out);
}

// round 6
// speedup vs baseline: 1.0108x; 1.0108x over previous
#include <cuda_runtime.h>

// DeepFilter: out_r = box3x5( xr*fr - xi*fi ),  out_i = 2 * box3x5( xr*fi )
// Smem-free: time halo via warp shuffles, freq via rolling 3-row window.
// Each warp owns 4 output d-rows, streams 6 input rows (per-row predication
// kept deliberately: it throttles LDG front-batching, avoiding cross-CTA
// L1tex-queue contention observed in R5).
// Shapes: B=8, D=256, T=2048, L=2, I=1. Output [B, 2D, T].

static constexpr int Bn = 8;
static constexpr int Dn = 256;
static constexpr int Tn = 2048;

static constexpr int NTHREADS = 128;   // 4 warps
static constexpr int T_TILE   = 128;   // 32 lanes x float4
static constexpr int D_STRIP  = 4;     // output rows per warp
static constexpr int D_TILE   = (NTHREADS / 32) * D_STRIP;   // 16 rows / block

__device__ __forceinline__ float4 ld4(const float* p) {
    return *reinterpret_cast<const float4*>(p);
}
__device__ __forceinline__ float2 ld2(const float* p) {
    return *reinterpret_cast<const float2*>(p);
}

__global__ __launch_bounds__(NTHREADS, 9)
void deepfilter_kernel(const float* __restrict__ xr,
                       const float* __restrict__ xi,
                       const float* __restrict__ fr,
                       const float* __restrict__ fi,
                       float* __restrict__ out)
{
    const int b    = blockIdx.z;
    const int t0   = blockIdx.x * T_TILE;
    const int d0   = blockIdx.y * D_TILE;
    const int warp = threadIdx.x >> 5;
    const int lane = threadIdx.x & 31;
    const int t    = t0 + 4 * lane;

    const size_t base  = (size_t)b * Dn * Tn;
    const int    dbase = d0 + D_STRIP * warp;   // output rows dbase .. dbase+3

    // Warp-edge time halo: lane 0 needs cols t0-2,t0-1; lane 31 needs
    // t0+128,t0+129. Both are 8B-aligned float2 loads used identically.
    const int  ht    = (lane == 0) ? (t0 - 2) : (t0 + T_TILE);
    const bool hlane = (lane == 0) | (lane == 31);
    const bool hok_t = (ht >= 0) & (ht < Tn);

    // rolling time-sum state: s[r-1], s[r-2]
    float4 m1r = {0,0,0,0}, m1i = {0,0,0,0};
    float4 m2r = {0,0,0,0}, m2i = {0,0,0,0};

    const size_t ob = (size_t)b * (2 * Dn) * Tn;
    const size_t oI = (size_t)Dn * Tn;

    #pragma unroll
    for (int r = 0; r < D_STRIP + 2; ++r) {
        const int  d   = dbase - 1 + r;
        const bool dok = (unsigned)d < (unsigned)Dn;

        float4 a = {0,0,0,0}, c = {0,0,0,0}, e = {0,0,0,0}, f = {0,0,0,0};
        float2 ha = {0,0}, hc = {0,0}, he = {0,0}, hf = {0,0};

        if (dok) {
            const size_t idx = base + (size_t)d * Tn + t;
            a = ld4(xr + idx); c = ld4(xi + idx);
            e = ld4(fr + idx); f = ld4(fi + idx);
            if (hlane & hok_t) {
                const size_t hidx = base + (size_t)d * Tn + ht;
                ha = ld2(xr + hidx); hc = ld2(xi + hidx);
                he = ld2(fr + hidx); hf = ld2(fi + hidx);
            }
        }

        // pointwise products (imag WITHOUT the 2x — folded into store)
        const float pr0 = fmaf(a.x, e.x, -c.x * f.x);
        const float pr1 = fmaf(a.y, e.y, -c.y * f.y);
        const float pr2 = fmaf(a.z, e.z, -c.z * f.z);
        const float pr3 = fmaf(a.w, e.w, -c.w * f.w);
        const float pi0 = a.x * f.x;
        const float pi1 = a.y * f.y;
        const float pi2 = a.z * f.z;
        const float pi3 = a.w * f.w;

        // halo products (lane0: t-2,t-1 ; lane31: t+4,t+5)
        const float hpr0 = fmaf(ha.x, he.x, -hc.x * hf.x);
        const float hpr1 = fmaf(ha.y, he.y, -hc.y * hf.y);
        const float hpi0 = ha.x * hf.x;
        const float hpi1 = ha.y * hf.y;

        // neighbor exchange: lm* = p[-2],p[-1]; rp* = p[+4],p[+5]
        float lmr2 = __shfl_up_sync(0xffffffffu, pr2, 1);
        float lmr1 = __shfl_up_sync(0xffffffffu, pr3, 1);
        float rpr4 = __shfl_down_sync(0xffffffffu, pr0, 1);
        float rpr5 = __shfl_down_sync(0xffffffffu, pr1, 1);
        float lmi2 = __shfl_up_sync(0xffffffffu, pi2, 1);
        float lmi1 = __shfl_up_sync(0xffffffffu, pi3, 1);
        float rpi4 = __shfl_down_sync(0xffffffffu, pi0, 1);
        float rpi5 = __shfl_down_sync(0xffffffffu, pi1, 1);
        if (lane == 0)  { lmr2 = hpr0; lmr1 = hpr1; lmi2 = hpi0; lmi1 = hpi1; }
        if (lane == 31) { rpr4 = hpr0; rpr5 = hpr1; rpi4 = hpi0; rpi5 = hpi1; }

        // sliding 5-tap time sums for this input row
        float4 sr, si;
        sr.x = lmr2 + lmr1 + pr0 + pr1 + pr2;
        sr.y = sr.x - lmr2 + pr3;
        sr.z = sr.y - lmr1 + rpr4;
        sr.w = sr.z - pr0 + rpr5;
        si.x = lmi2 + lmi1 + pi0 + pi1 + pi2;
        si.y = si.x - lmi2 + pi3;
        si.z = si.y - lmi1 + rpi4;
        si.w = si.z - pi0 + rpi5;

        // rolling 3-row freq sum: emit output row dbase + r - 2
        if (r >= 2) {
            const int d_out = dbase + r - 2;
            float4 orr, oii;
            orr.x = m2r.x + m1r.x + sr.x;
            orr.y = m2r.y + m1r.y + sr.y;
            orr.z = m2r.z + m1r.z + sr.z;
            orr.w = m2r.w + m1r.w + sr.w;
            oii.x = 2.f * (m2i.x + m1i.x + si.x);
            oii.y = 2.f * (m2i.y + m1i.y + si.y);
            oii.z = 2.f * (m2i.z + m1i.z + si.z);
            oii.w = 2.f * (m2i.w + m1i.w + si.w);
            const size_t o = ob + (size_t)d_out * Tn + t;
            __stcs(reinterpret_cast<float4*>(out + o),      orr);
            __stcs(reinterpret_cast<float4*>(out + o + oI), oii);
        }
        m2r = m1r; m2i = m1i;
        m1r = sr;  m1i = si;
    }
}

extern "C" void kernel_launch(void* const* d_in, const int* in_sizes, int n_in,
                              void* d_out, int out_size)
{
    (void)in_sizes; (void)n_in; (void)out_size;
    const float* xr = (const float*)d_in[0];
    const float* xi = (const float*)d_in[1];
    const float* fr = (const float*)d_in[2];
    const float* fi = (const float*)d_in[3];
    float* out = (float*)d_out;

    dim3 grid(Tn / T_TILE, Dn / D_TILE, Bn);   // (16, 16, 8) = 2048 blocks
    deepfilter_kernel<<<grid, NTHREADS>>>(xr, xi, fr, fi, out);
}

// round 7
// speedup vs baseline: 1.0625x; 1.0511x over previous
#include <cuda_runtime.h>

// DeepFilter: out_r = box3x5( xr*fr - xi*fi ),  out_i = 2 * box3x5( xr*fi )
// Smem-free: time halo via warp shuffles, freq direction via a rolling
// 3-row window. Each warp owns 8 output d-rows and streams 10 input rows.
// (Structure identical to the best R4 kernel; only the occupancy bound
//  changes 8 -> 9 to cap registers at 56 and fit one more resident block.)
// Shapes: B=8, D=256, T=2048, L=2, I=1. Output [B, 2D, T].

static constexpr int Bn = 8;
static constexpr int Dn = 256;
static constexpr int Tn = 2048;

static constexpr int NTHREADS = 128;   // 4 warps
static constexpr int T_TILE   = 128;   // 32 lanes x float4
static constexpr int D_STRIP  = 8;     // output rows per warp
static constexpr int D_TILE   = (NTHREADS / 32) * D_STRIP;   // 32 rows / block

__device__ __forceinline__ float4 ld4(const float* p) {
    return *reinterpret_cast<const float4*>(p);
}
__device__ __forceinline__ float2 ld2(const float* p) {
    return *reinterpret_cast<const float2*>(p);
}

__global__ __launch_bounds__(NTHREADS, 9)
void deepfilter_kernel(const float* __restrict__ xr,
                       const float* __restrict__ xi,
                       const float* __restrict__ fr,
                       const float* __restrict__ fi,
                       float* __restrict__ out)
{
    const int b    = blockIdx.z;
    const int t0   = blockIdx.x * T_TILE;
    const int d0   = blockIdx.y * D_TILE;
    const int warp = threadIdx.x >> 5;
    const int lane = threadIdx.x & 31;
    const int t    = t0 + 4 * lane;

    const size_t base  = (size_t)b * Dn * Tn;
    const int    dbase = d0 + D_STRIP * warp;   // output rows dbase .. dbase+7

    // Warp-edge time halo: lane 0 needs cols t0-2,t0-1; lane 31 needs
    // t0+128,t0+129. Both are 8B-aligned float2 loads used identically.
    const int  ht    = (lane == 0) ? (t0 - 2) : (t0 + T_TILE);
    const bool hlane = (lane == 0) | (lane == 31);
    const bool hok_t = (ht >= 0) & (ht < Tn);

    // rolling time-sum state: s[r-1], s[r-2]
    float4 m1r = {0,0,0,0}, m1i = {0,0,0,0};
    float4 m2r = {0,0,0,0}, m2i = {0,0,0,0};

    const size_t ob = (size_t)b * (2 * Dn) * Tn;
    const size_t oI = (size_t)Dn * Tn;

    #pragma unroll
    for (int r = 0; r < D_STRIP + 2; ++r) {
        const int  d   = dbase - 1 + r;
        const bool dok = (unsigned)d < (unsigned)Dn;

        float4 a = {0,0,0,0}, c = {0,0,0,0}, e = {0,0,0,0}, f = {0,0,0,0};
        float2 ha = {0,0}, hc = {0,0}, he = {0,0}, hf = {0,0};

        if (dok) {
            const size_t idx = base + (size_t)d * Tn + t;
            a = ld4(xr + idx); c = ld4(xi + idx);
            e = ld4(fr + idx); f = ld4(fi + idx);
            if (hlane & hok_t) {
                const size_t hidx = base + (size_t)d * Tn + ht;
                ha = ld2(xr + hidx); hc = ld2(xi + hidx);
                he = ld2(fr + hidx); hf = ld2(fi + hidx);
            }
        }

        // pointwise products (imag part WITHOUT the 2x — folded into store)
        const float pr0 = fmaf(a.x, e.x, -c.x * f.x);
        const float pr1 = fmaf(a.y, e.y, -c.y * f.y);
        const float pr2 = fmaf(a.z, e.z, -c.z * f.z);
        const float pr3 = fmaf(a.w, e.w, -c.w * f.w);
        const float pi0 = a.x * f.x;
        const float pi1 = a.y * f.y;
        const float pi2 = a.z * f.z;
        const float pi3 = a.w * f.w;

        // halo products (lane0: t-2,t-1 ; lane31: t+4,t+5)
        const float hpr0 = fmaf(ha.x, he.x, -hc.x * hf.x);
        const float hpr1 = fmaf(ha.y, he.y, -hc.y * hf.y);
        const float hpi0 = ha.x * hf.x;
        const float hpi1 = ha.y * hf.y;

        // neighbor exchange: lm* = p[-2],p[-1]; rp* = p[+4],p[+5]
        float lmr2 = __shfl_up_sync(0xffffffffu, pr2, 1);
        float lmr1 = __shfl_up_sync(0xffffffffu, pr3, 1);
        float rpr4 = __shfl_down_sync(0xffffffffu, pr0, 1);
        float rpr5 = __shfl_down_sync(0xffffffffu, pr1, 1);
        float lmi2 = __shfl_up_sync(0xffffffffu, pi2, 1);
        float lmi1 = __shfl_up_sync(0xffffffffu, pi3, 1);
        float rpi4 = __shfl_down_sync(0xffffffffu, pi0, 1);
        float rpi5 = __shfl_down_sync(0xffffffffu, pi1, 1);
        if (lane == 0)  { lmr2 = hpr0; lmr1 = hpr1; lmi2 = hpi0; lmi1 = hpi1; }
        if (lane == 31) { rpr4 = hpr0; rpr5 = hpr1; rpi4 = hpi0; rpi5 = hpi1; }

        // sliding 5-tap time sums for this input row
        float4 sr, si;
        sr.x = lmr2 + lmr1 + pr0 + pr1 + pr2;
        sr.y = sr.x - lmr2 + pr3;
        sr.z = sr.y - lmr1 + rpr4;
        sr.w = sr.z - pr0 + rpr5;
        si.x = lmi2 + lmi1 + pi0 + pi1 + pi2;
        si.y = si.x - lmi2 + pi3;
        si.z = si.y - lmi1 + rpi4;
        si.w = si.z - pi0 + rpi5;

        // rolling 3-row freq sum: emit output row dbase + r - 2
        if (r >= 2) {
            const int d_out = dbase + r - 2;
            float4 orr, oii;
            orr.x = m2r.x + m1r.x + sr.x;
            orr.y = m2r.y + m1r.y + sr.y;
            orr.z = m2r.z + m1r.z + sr.z;
            orr.w = m2r.w + m1r.w + sr.w;
            oii.x = 2.f * (m2i.x + m1i.x + si.x);
            oii.y = 2.f * (m2i.y + m1i.y + si.y);
            oii.z = 2.f * (m2i.z + m1i.z + si.z);
            oii.w = 2.f * (m2i.w + m1i.w + si.w);
            const size_t o = ob + (size_t)d_out * Tn + t;
            __stcs(reinterpret_cast<float4*>(out + o),      orr);
            __stcs(reinterpret_cast<float4*>(out + o + oI), oii);
        }
        m2r = m1r; m2i = m1i;
        m1r = sr;  m1i = si;
    }
}

extern "C" void kernel_launch(void* const* d_in, const int* in_sizes, int n_in,
                              void* d_out, int out_size)
{
    (void)in_sizes; (void)n_in; (void)out_size;
    const float* xr = (const float*)d_in[0];
    const float* xi = (const float*)d_in[1];
    const float* fr = (const float*)d_in[2];
    const float* fi = (const float*)d_in[3];
    float* out = (float*)d_out;

    dim3 grid(Tn / T_TILE, Dn / D_TILE, Bn);   // (16, 8, 8) = 1024 blocks
    deepfilter_kernel<<<grid, NTHREADS>>>(xr, xi, fr, fi, out);
}

// round 8
// speedup vs baseline: 1.2143x; 1.1429x over previous
#include <cuda_runtime.h>

// DeepFilter: out_r = box3x5( xr*fr - xi*fi ),  out_i = 2 * box3x5( xr*fi )
// Smem-free: time halo via warp shuffles, freq direction via a rolling
// 3-row window. Each warp owns 8 output d-rows and streams 10 input rows.
// This is the empirically optimal configuration (R4): 64 regs buys load
// batching (MLP); per-row predication throttles LDG front-batching just
// enough to avoid cross-CTA L1tex-queue contention.
// Shapes: B=8, D=256, T=2048, L=2, I=1. Output [B, 2D, T].

static constexpr int Bn = 8;
static constexpr int Dn = 256;
static constexpr int Tn = 2048;

static constexpr int NTHREADS = 128;   // 4 warps
static constexpr int T_TILE   = 128;   // 32 lanes x float4
static constexpr int D_STRIP  = 8;     // output rows per warp
static constexpr int D_TILE   = (NTHREADS / 32) * D_STRIP;   // 32 rows / block

__device__ __forceinline__ float4 ld4(const float* p) {
    return *reinterpret_cast<const float4*>(p);
}
__device__ __forceinline__ float2 ld2(const float* p) {
    return *reinterpret_cast<const float2*>(p);
}

__global__ __launch_bounds__(NTHREADS, 8)
void deepfilter_kernel(const float* __restrict__ xr,
                       const float* __restrict__ xi,
                       const float* __restrict__ fr,
                       const float* __restrict__ fi,
                       float* __restrict__ out)
{
    const int b    = blockIdx.z;
    const int t0   = blockIdx.x * T_TILE;
    const int d0   = blockIdx.y * D_TILE;
    const int warp = threadIdx.x >> 5;
    const int lane = threadIdx.x & 31;
    const int t    = t0 + 4 * lane;

    const size_t base  = (size_t)b * Dn * Tn;
    const int    dbase = d0 + D_STRIP * warp;   // output rows dbase .. dbase+7

    // Warp-edge time halo: lane 0 needs cols t0-2,t0-1; lane 31 needs
    // t0+128,t0+129. Both are 8B-aligned float2 loads used identically.
    const int  ht    = (lane == 0) ? (t0 - 2) : (t0 + T_TILE);
    const bool hlane = (lane == 0) | (lane == 31);
    const bool hok_t = (ht >= 0) & (ht < Tn);

    // rolling time-sum state: s[r-1], s[r-2]
    float4 m1r = {0,0,0,0}, m1i = {0,0,0,0};
    float4 m2r = {0,0,0,0}, m2i = {0,0,0,0};

    const size_t ob = (size_t)b * (2 * Dn) * Tn;
    const size_t oI = (size_t)Dn * Tn;

    #pragma unroll
    for (int r = 0; r < D_STRIP + 2; ++r) {
        const int  d   = dbase - 1 + r;
        const bool dok = (unsigned)d < (unsigned)Dn;

        float4 a = {0,0,0,0}, c = {0,0,0,0}, e = {0,0,0,0}, f = {0,0,0,0};
        float2 ha = {0,0}, hc = {0,0}, he = {0,0}, hf = {0,0};

        if (dok) {
            const size_t idx = base + (size_t)d * Tn + t;
            a = ld4(xr + idx); c = ld4(xi + idx);
            e = ld4(fr + idx); f = ld4(fi + idx);
            if (hlane & hok_t) {
                const size_t hidx = base + (size_t)d * Tn + ht;
                ha = ld2(xr + hidx); hc = ld2(xi + hidx);
                he = ld2(fr + hidx); hf = ld2(fi + hidx);
            }
        }

        // pointwise products (imag part WITHOUT the 2x — folded into store)
        const float pr0 = fmaf(a.x, e.x, -c.x * f.x);
        const float pr1 = fmaf(a.y, e.y, -c.y * f.y);
        const float pr2 = fmaf(a.z, e.z, -c.z * f.z);
        const float pr3 = fmaf(a.w, e.w, -c.w * f.w);
        const float pi0 = a.x * f.x;
        const float pi1 = a.y * f.y;
        const float pi2 = a.z * f.z;
        const float pi3 = a.w * f.w;

        // halo products (lane0: t-2,t-1 ; lane31: t+4,t+5)
        const float hpr0 = fmaf(ha.x, he.x, -hc.x * hf.x);
        const float hpr1 = fmaf(ha.y, he.y, -hc.y * hf.y);
        const float hpi0 = ha.x * hf.x;
        const float hpi1 = ha.y * hf.y;

        // neighbor exchange: lm* = p[-2],p[-1]; rp* = p[+4],p[+5]
        float lmr2 = __shfl_up_sync(0xffffffffu, pr2, 1);
        float lmr1 = __shfl_up_sync(0xffffffffu, pr3, 1);
        float rpr4 = __shfl_down_sync(0xffffffffu, pr0, 1);
        float rpr5 = __shfl_down_sync(0xffffffffu, pr1, 1);
        float lmi2 = __shfl_up_sync(0xffffffffu, pi2, 1);
        float lmi1 = __shfl_up_sync(0xffffffffu, pi3, 1);
        float rpi4 = __shfl_down_sync(0xffffffffu, pi0, 1);
        float rpi5 = __shfl_down_sync(0xffffffffu, pi1, 1);
        if (lane == 0)  { lmr2 = hpr0; lmr1 = hpr1; lmi2 = hpi0; lmi1 = hpi1; }
        if (lane == 31) { rpr4 = hpr0; rpr5 = hpr1; rpi4 = hpi0; rpi5 = hpi1; }

        // sliding 5-tap time sums for this input row
        float4 sr, si;
        sr.x = lmr2 + lmr1 + pr0 + pr1 + pr2;
        sr.y = sr.x - lmr2 + pr3;
        sr.z = sr.y - lmr1 + rpr4;
        sr.w = sr.z - pr0 + rpr5;
        si.x = lmi2 + lmi1 + pi0 + pi1 + pi2;
        si.y = si.x - lmi2 + pi3;
        si.z = si.y - lmi1 + rpi4;
        si.w = si.z - pi0 + rpi5;

        // rolling 3-row freq sum: emit output row dbase + r - 2
        if (r >= 2) {
            const int d_out = dbase + r - 2;
            float4 orr, oii;
            orr.x = m2r.x + m1r.x + sr.x;
            orr.y = m2r.y + m1r.y + sr.y;
            orr.z = m2r.z + m1r.z + sr.z;
            orr.w = m2r.w + m1r.w + sr.w;
            oii.x = 2.f * (m2i.x + m1i.x + si.x);
            oii.y = 2.f * (m2i.y + m1i.y + si.y);
            oii.z = 2.f * (m2i.z + m1i.z + si.z);
            oii.w = 2.f * (m2i.w + m1i.w + si.w);
            const size_t o = ob + (size_t)d_out * Tn + t;
            __stcs(reinterpret_cast<float4*>(out + o),      orr);
            __stcs(reinterpret_cast<float4*>(out + o + oI), oii);
        }
        m2r = m1r; m2i = m1i;
        m1r = sr;  m1i = si;
    }
}

extern "C" void kernel_launch(void* const* d_in, const int* in_sizes, int n_in,
                              void* d_out, int out_size)
{
    (void)in_sizes; (void)n_in; (void)out_size;
    const float* xr = (const float*)d_in[0];
    const float* xi = (const float*)d_in[1];
    const float* fr = (const float*)d_in[2];
    const float* fi = (const float*)d_in[3];
    float* out = (float*)d_out;

    dim3 grid(Tn / T_TILE, Dn / D_TILE, Bn);   // (16, 8, 8) = 1024 blocks
    deepfilter_kernel<<<grid, NTHREADS>>>(xr, xi, fr, fi, out);
}